// round 6
// baseline (speedup 1.0000x reference)
#include <cuda_runtime.h>
#include <math.h>

// Shapes fixed by the problem: B=4, C=256, H=W=64, N=4096, Ci=128
#define B_  4
#define C_  256
#define N_  4096
#define CI_ 128

#define TJ_          16            // pixels per tile
#define TILES_       256           // tiles per batch (N_/TJ_)
#define TOTAL_TILES_ 1024          // B_ * TILES_
#define GRID_        512           // blocks; each handles 2 tiles
#define TPB_         256

// Scratch (allocation-free rule: __device__ globals)
__device__ float g_part[TOTAL_TILES_ * C_];  // per-tile channel sums (1 MB, L2)
__device__ float g_xbar[B_ * C_];
__device__ float g_w[B_ * C_];
__device__ float g_s[B_];
__device__ unsigned g_barcnt[4];             // zero-init; self-resetting
__device__ unsigned g_bargen[4];             // monotone generation counters

// Sense-reversal grid barrier. Safe: launch_bounds(256,4) guarantees >=4
// CTAs/SM -> 512 blocks all resident on sm_100a (148 SMs, 592 slots).
// Guarded spin: bails after ~4M polls instead of hanging the container.
__device__ __forceinline__ void grid_barrier(int id, int tid) {
    __syncthreads();
    if (tid == 0) {
        __threadfence();                       // release prior writes
        volatile unsigned* genp = &g_bargen[id];
        unsigned g0 = *genp;                   // read BEFORE arriving
        unsigned old = atomicAdd(&g_barcnt[id], 1u);
        if (old == GRID_ - 1u) {
            g_barcnt[id] = 0u;
            __threadfence();
            atomicAdd(&g_bargen[id], 1u);
        } else {
            int guard = 0;
            while (*genp == g0 && guard < (1 << 22)) { __nanosleep(64); ++guard; }
        }
        __threadfence();                       // acquire
    }
    __syncthreads();
}

__global__ __launch_bounds__(TPB_, 4) void k_all(
    const float* __restrict__ x,
    const float* __restrict__ theta_w, const float* __restrict__ theta_b,
    const float* __restrict__ phi_w,  const float* __restrict__ phi_b,
    float* __restrict__ out)
{
    const int tid  = threadIdx.x;
    const int lane = tid & 31, warp = tid >> 5;
    const int jj   = tid & 15;                 // pixel within tile
    const int cc   = tid >> 4;                 // channel group 0..15 (16 ch each)

    __shared__ float sums_s[C_];
    __shared__ float ws[C_];
    __shared__ float part_s[8 * 16];
    __shared__ float conf_s[TJ_];
    __shared__ float sb_s;
    __shared__ float xb_s[C_];
    __shared__ float tb_s[CI_];

    float xv[2][16];                           // x cached in registers

    // ---- Phase 1a: read x once; per-tile channel sums -> g_part ----
    #pragma unroll
    for (int s = 0; s < 2; ++s) {
        const int tile = blockIdx.x + s * GRID_;        // 0..1023
        const int b = tile >> 8;
        const int t = tile & (TILES_ - 1);
        const int j0 = t * TJ_;
        const float* xb = x + (size_t)(b * C_) * N_ + j0 + jj;
        #pragma unroll
        for (int i = 0; i < 16; ++i) {
            const int c = cc * 16 + i;
            float v = __ldg(xb + (size_t)c * N_);
            xv[s][i] = v;
            // reduce over the 16 jj-lanes (xor offsets < 16 stay in-group)
            v += __shfl_xor_sync(0xffffffffu, v, 1);
            v += __shfl_xor_sync(0xffffffffu, v, 2);
            v += __shfl_xor_sync(0xffffffffu, v, 4);
            v += __shfl_xor_sync(0xffffffffu, v, 8);
            if (jj == 0) sums_s[c] = v;
        }
        __syncthreads();
        g_part[(size_t)tile * C_ + tid] = sums_s[tid];  // coalesced 1KB row
        __syncthreads();
    }

    grid_barrier(0, tid);

    // ---- Phase 1b: xbar[b,c] = (1/N) * sum_t g_part[tile(b,t), c] ----
    if (warp < 2) {
        const int row = blockIdx.x * 2 + warp;          // 0..1023 = b*256 + c
        const int b = row >> 8, c = row & 255;
        float a = 0.f;
        #pragma unroll
        for (int k = 0; k < TILES_ / 32; ++k) {
            const int t = lane + k * 32;
            a += __ldcg(&g_part[(size_t)(b * TILES_ + t) * C_ + c]);
        }
        #pragma unroll
        for (int o = 16; o; o >>= 1) a += __shfl_xor_sync(0xffffffffu, a, o);
        if (lane == 0) g_xbar[row] = a * (1.0f / N_);
    }

    grid_barrier(1, tid);

    // ---- Phase 2: blocks 0..3 compute w[b,:], s[b] (tiny matvecs) ----
    if (blockIdx.x < B_) {
        const int b = blockIdx.x;
        xb_s[tid] = __ldcg(&g_xbar[b * C_ + tid]);
        __syncthreads();
        for (int i = 0; i < CI_ / 8; ++i) {
            int k = warp * (CI_ / 8) + i;
            const float* tw = theta_w + (size_t)k * C_;
            float a = 0.f;
            #pragma unroll
            for (int c = lane; c < C_; c += 32) a += __ldg(tw + c) * xb_s[c];
            #pragma unroll
            for (int o = 16; o; o >>= 1) a += __shfl_xor_sync(0xffffffffu, a, o);
            if (lane == 0) tb_s[k] = a + __ldg(theta_b + k);
        }
        __syncthreads();
        float wacc = 0.f;
        #pragma unroll 8
        for (int k = 0; k < CI_; ++k)
            wacc += tb_s[k] * __ldg(phi_w + (size_t)k * C_ + tid);
        g_w[b * C_ + tid] = wacc;
        if (warp == 0) {
            float a = 0.f;
            #pragma unroll
            for (int k = lane; k < CI_; k += 32) a += tb_s[k] * __ldg(phi_b + k);
            #pragma unroll
            for (int o = 16; o; o >>= 1) a += __shfl_xor_sync(0xffffffffu, a, o);
            if (lane == 0) g_s[b] = a;
        }
    }

    grid_barrier(2, tid);

    // ---- Phase 3: per-pixel dot -> sigmoid -> scale, all from registers ----
    #pragma unroll
    for (int s = 0; s < 2; ++s) {
        const int tile = blockIdx.x + s * GRID_;
        const int b = tile >> 8;
        const int t = tile & (TILES_ - 1);
        const int j0 = t * TJ_;

        ws[tid] = __ldcg(&g_w[b * C_ + tid]);
        if (tid == 0) sb_s = __ldcg(&g_s[b]);
        __syncthreads();

        float acc = 0.f;
        #pragma unroll
        for (int i = 0; i < 16; ++i) acc += ws[cc * 16 + i] * xv[s][i];
        acc += __shfl_xor_sync(0xffffffffu, acc, 16);   // fold cc pairs
        if (lane < 16) part_s[warp * 16 + lane] = acc;
        __syncthreads();
        if (tid < TJ_) {
            float m = 0.f;
            #pragma unroll
            for (int w = 0; w < 8; ++w) m += part_s[w * 16 + tid];
            m = (m + sb_s) * (1.0f / N_);
            conf_s[tid] = 1.0f / (1.0f + expf(-m));
        }
        __syncthreads();
        const float cf = conf_s[jj];
        float* ob = out + (size_t)(b * C_) * N_ + j0 + jj;
        #pragma unroll
        for (int i = 0; i < 16; ++i) {
            const int c = cc * 16 + i;
            ob[(size_t)c * N_] = cf * xv[s][i];
        }
        __syncthreads();                                // ws/conf reuse guard
    }
}

// ---------------------------------------------------------------------------
extern "C" void kernel_launch(void* const* d_in, const int* in_sizes, int n_in,
                              void* d_out, int out_size) {
    const float* x       = (const float*)d_in[0];
    const float* theta_w = (const float*)d_in[1];
    const float* theta_b = (const float*)d_in[2];
    const float* phi_w   = (const float*)d_in[3];
    const float* phi_b   = (const float*)d_in[4];
    float* out = (float*)d_out;

    k_all<<<GRID_, TPB_>>>(x, theta_w, theta_b, phi_w, phi_b, out);
}